// round 1
// baseline (speedup 1.0000x reference)
#include <cuda_runtime.h>
#include <math.h>

// Problem constants
#define BB   8192      // batch
#define TT   20        // seq len
#define FF   812       // nfeatures
#define HH   400       // hidden
#define GG   1600      // 4*HID
#define LDW  813       // W_ih leading dim (NF+1)
#define VARI 811       // imputed feature index

// GEMM tiling
#define BM 64
#define BN 64
#define BK 16
#define PAD 4

// ---------------- device scratch (static; no runtime allocation) ----------------
__device__ float g_gates_pre[(size_t)BB * TT * GG];  // [b*T+t][1600]  (~1.05 GB)
__device__ float g_gates[(size_t)BB * GG];           // per-step gates (52 MB)
__device__ float g_h[(size_t)BB * HH];
__device__ float g_c[(size_t)BB * HH];
__device__ float g_xvar[BB];
__device__ float g_num[TT];
__device__ float g_den[TT];
__device__ float g_wsum[HH];
__device__ float g_w811[GG];   // W_ih[:, 811]
__device__ float g_w812[GG];   // W_ih[:, 812] (mask column)
__device__ float g_bias[GG];   // b_ih + b_hh

// ---------------- small setup kernels ----------------
__global__ void init_kernel() {
    size_t i = (size_t)blockIdx.x * blockDim.x + threadIdx.x;
    size_t n = (size_t)BB * HH;
    if (i < n) { g_h[i] = 0.f; g_c[i] = 0.f; }
    if (i < TT) g_num[i] = 0.f;
}

__global__ void prep_kernel(const float* __restrict__ W_ih,
                            const float* __restrict__ b_ih,
                            const float* __restrict__ b_hh) {
    int n = blockIdx.x * blockDim.x + threadIdx.x;
    if (n < GG) {
        g_w811[n] = W_ih[(size_t)n * LDW + VARI];
        g_w812[n] = W_ih[(size_t)n * LDW + FF];
        g_bias[n] = b_ih[n] + b_hh[n];
    }
}

__global__ void wsum_kernel(const float* __restrict__ W_decay) {
    int j = blockIdx.x;               // 0..HH-1
    int tid = threadIdx.x;            // 128
    float s = 0.f;
    for (int f = tid; f < FF; f += 128) s += W_decay[(size_t)j * FF + f];
    __shared__ float red[128];
    red[tid] = s; __syncthreads();
    for (int st = 64; st > 0; st >>= 1) {
        if (tid < st) red[tid] += red[tid + st];
        __syncthreads();
    }
    if (tid == 0) g_wsum[j] = red[0];
}

__global__ void den_kernel(const float* __restrict__ masks) {
    int t = blockIdx.x;               // 0..TT-1
    int tid = threadIdx.x;            // 256
    float s = 0.f;
    for (int b = tid; b < BB; b += 256) s += masks[(size_t)b * TT + t];
    __shared__ float red[256];
    red[tid] = s; __syncthreads();
    for (int st = 128; st > 0; st >>= 1) {
        if (tid < st) red[tid] += red[tid + st];
        __syncthreads();
    }
    if (tid == 0) g_den[t] = red[0];
}

// ---------------- precompute GEMM: gates_pre = values @ W_ih[:, :812]^T + folds ----------------
// A: values [M=BB*TT, FF] row-major (row r = b*TT + t). W: W_ih [GG, LDW].
// Epilogue: + m[r]*w812[n] + bias[n] - values[r,811]*w811[n]  (excludes VAR column from the sum)
__global__ __launch_bounds__(256)
void gemm_pre_kernel(const float* __restrict__ A,
                     const float* __restrict__ W,
                     const float* __restrict__ masks) {
    __shared__ float As[BK][BM + PAD];
    __shared__ float Bs[BK][BN + PAD];
    const int tid = threadIdx.x;
    const int tx = tid & 15, ty = tid >> 4;
    const int row0 = blockIdx.y * BM;
    const int col0 = blockIdx.x * BN;
    float acc[4][4] = {};

    for (int k0 = 0; k0 < FF; k0 += BK) {
        #pragma unroll
        for (int i = 0; i < 4; i++) {
            int idx = tid + i * 256;
            int m = idx >> 4, k = idx & 15;
            int gk = k0 + k;
            As[k][m] = (gk < FF) ? A[(size_t)(row0 + m) * FF + gk] : 0.f;
        }
        #pragma unroll
        for (int i = 0; i < 4; i++) {
            int idx = tid + i * 256;
            int n = idx >> 4, k = idx & 15;
            int gk = k0 + k;
            Bs[k][n] = (gk < FF) ? W[(size_t)(col0 + n) * LDW + gk] : 0.f;
        }
        __syncthreads();
        #pragma unroll
        for (int k = 0; k < BK; k++) {
            float a[4], b[4];
            #pragma unroll
            for (int i = 0; i < 4; i++) a[i] = As[k][ty * 4 + i];
            #pragma unroll
            for (int j = 0; j < 4; j++) b[j] = Bs[k][tx * 4 + j];
            #pragma unroll
            for (int i = 0; i < 4; i++)
                #pragma unroll
                for (int j = 0; j < 4; j++)
                    acc[i][j] += a[i] * b[j];
        }
        __syncthreads();
    }

    #pragma unroll
    for (int i = 0; i < 4; i++) {
        int r = row0 + ty * 4 + i;
        float mk = masks[r];
        float v811 = A[(size_t)r * FF + VARI];
        #pragma unroll
        for (int j = 0; j < 4; j++) {
            int n = col0 + tx * 4 + j;
            g_gates_pre[(size_t)r * GG + n] =
                acc[i][j] + mk * g_w812[n] + g_bias[n] - v811 * g_w811[n];
        }
    }
}

// ---------------- per-step decay + imputation + loss numerator ----------------
__global__ void decay_kernel(const float* __restrict__ deltas,
                             const float* __restrict__ masks,
                             const float* __restrict__ values,
                             const float* __restrict__ b_decay,
                             const float* __restrict__ W_reg,
                             const float* __restrict__ b_reg,
                             float* __restrict__ imp, int write_loss, int t) {
    int b = blockIdx.x;
    int tid = threadIdx.x;  // 128
    float d = deltas[(size_t)b * TT + t];
    float m = masks[(size_t)b * TT + t];
    float local = 0.f;
    for (int j = tid; j < HH; j += 128) {
        float a = d * g_wsum[j] + b_decay[j];
        float gamma = expf(-fmaxf(a, 0.f));
        float hv = g_h[(size_t)b * HH + j] * gamma;
        g_h[(size_t)b * HH + j] = hv;
        local += hv * W_reg[j];
    }
    __shared__ float red[128];
    red[tid] = local; __syncthreads();
    for (int s = 64; s > 0; s >>= 1) {
        if (tid < s) red[tid] += red[tid + s];
        __syncthreads();
    }
    if (tid == 0) {
        float xh = red[0] + b_reg[0];
        float xval = values[((size_t)b * TT + t) * FF + VARI];
        float xv = xval * m + (1.f - m) * xh;
        g_xvar[b] = xv;
        imp[(size_t)b * TT + t] = xv;
        if (write_loss) atomicAdd(&g_num[t], fabsf(xv - xh) * m);
    }
}

// ---------------- per-step GEMM: gates = gates_pre[t] + xvar*w811 + h @ W_hh^T ----------------
__global__ __launch_bounds__(256)
void gemm_hh_kernel(const float* __restrict__ Whh, int t) {
    __shared__ float As[BK][BM + PAD];
    __shared__ float Bs[BK][BN + PAD];
    const int tid = threadIdx.x;
    const int tx = tid & 15, ty = tid >> 4;
    const int row0 = blockIdx.y * BM;   // batch
    const int col0 = blockIdx.x * BN;   // gate index
    float acc[4][4] = {};

    for (int k0 = 0; k0 < HH; k0 += BK) {   // 400 % 16 == 0, no guards
        #pragma unroll
        for (int i = 0; i < 4; i++) {
            int idx = tid + i * 256;
            int m = idx >> 4, k = idx & 15;
            As[k][m] = g_h[(size_t)(row0 + m) * HH + (k0 + k)];
        }
        #pragma unroll
        for (int i = 0; i < 4; i++) {
            int idx = tid + i * 256;
            int n = idx >> 4, k = idx & 15;
            Bs[k][n] = Whh[(size_t)(col0 + n) * HH + (k0 + k)];
        }
        __syncthreads();
        #pragma unroll
        for (int k = 0; k < BK; k++) {
            float a[4], b[4];
            #pragma unroll
            for (int i = 0; i < 4; i++) a[i] = As[k][ty * 4 + i];
            #pragma unroll
            for (int j = 0; j < 4; j++) b[j] = Bs[k][tx * 4 + j];
            #pragma unroll
            for (int i = 0; i < 4; i++)
                #pragma unroll
                for (int j = 0; j < 4; j++)
                    acc[i][j] += a[i] * b[j];
        }
        __syncthreads();
    }

    #pragma unroll
    for (int i = 0; i < 4; i++) {
        int r = row0 + ty * 4 + i;
        float xv = g_xvar[r];
        size_t prer = ((size_t)r * TT + t) * GG;
        #pragma unroll
        for (int j = 0; j < 4; j++) {
            int n = col0 + tx * 4 + j;
            g_gates[(size_t)r * GG + n] = acc[i][j] + g_gates_pre[prer + n] + xv * g_w811[n];
        }
    }
}

// ---------------- per-step LSTM pointwise update ----------------
__global__ void lstm_kernel() {
    size_t idx = (size_t)blockIdx.x * blockDim.x + threadIdx.x;  // BB*HH
    if (idx >= (size_t)BB * HH) return;
    size_t b = idx / HH;
    int j = (int)(idx % HH);
    const float* g = &g_gates[b * GG];
    float ig = g[j], fg = g[j + HH], gg = g[j + 2 * HH], og = g[j + 3 * HH];
    float c = g_c[idx];
    float si = 1.f / (1.f + expf(-ig));
    float sf = 1.f / (1.f + expf(-fg));
    float so = 1.f / (1.f + expf(-og));
    float tg = tanhf(gg);
    c = sf * c + si * tg;
    g_c[idx] = c;
    g_h[idx] = so * tanhf(c);
}

__global__ void loss_kernel(float* __restrict__ out) {
    if (threadIdx.x == 0 && blockIdx.x == 0) {
        float s = 0.f;
        for (int t = 0; t < TT; t++) s += g_num[t] / (g_den[t] + 1e-5f);
        out[0] = s / (float)TT;
    }
}

// ---------------- launch ----------------
extern "C" void kernel_launch(void* const* d_in, const int* in_sizes, int n_in,
                              void* d_out, int out_size) {
    const float* values  = (const float*)d_in[0];
    const float* masks   = (const float*)d_in[1];
    const float* deltas  = (const float*)d_in[2];
    const float* W_decay = (const float*)d_in[3];
    const float* b_decay = (const float*)d_in[4];
    const float* W_reg   = (const float*)d_in[5];
    const float* b_reg   = (const float*)d_in[6];
    const float* W_ih    = (const float*)d_in[7];
    const float* W_hh    = (const float*)d_in[8];
    const float* b_ih    = (const float*)d_in[9];
    const float* b_hh    = (const float*)d_in[10];
    float* out = (float*)d_out;

    // Output layout: [loss, imputations(B,T)] flattened. If out_size == B*T,
    // the harness only keeps imputations; handle both.
    int has_loss = (out_size > BB * TT) ? 1 : 0;
    float* imp = out + has_loss;

    size_t nInit = (size_t)BB * HH;
    init_kernel<<<(unsigned)((nInit + 255) / 256), 256>>>();
    prep_kernel<<<(GG + 255) / 256, 256>>>(W_ih, b_ih, b_hh);
    wsum_kernel<<<HH, 128>>>(W_decay);
    if (has_loss) den_kernel<<<TT, 256>>>(masks);

    dim3 gpre(GG / BN, (BB * TT) / BM);   // 25 x 2560
    gemm_pre_kernel<<<gpre, 256>>>(values, W_ih, masks);

    dim3 ghh(GG / BN, BB / BM);           // 25 x 128
    unsigned lstmGrid = (unsigned)(((size_t)BB * HH + 255) / 256);
    for (int t = 0; t < TT; t++) {
        decay_kernel<<<BB, 128>>>(deltas, masks, values, b_decay, W_reg, b_reg,
                                  imp, has_loss, t);
        gemm_hh_kernel<<<ghh, 256>>>(W_hh, t);
        lstm_kernel<<<lstmGrid, 256>>>();
    }
    if (has_loss) loss_kernel<<<1, 32>>>(out);
}